// round 1
// baseline (speedup 1.0000x reference)
#include <cuda_runtime.h>
#include <cuda_bf16.h>

#define FULL 0xffffffffu

// Precomputed per-launch constants (params-only): CRZ diagonal phases and
// RY1/RY2 half-angle cos/sin. __device__ globals (no allocation allowed).
__device__ float2 g_diag1[256];
__device__ float2 g_diag2[256];
__device__ float2 g_cs1[8];
__device__ float2 g_cs2[8];

// bits[d, i] = (d >> (7-i)) & 1  (wire i <-> bit 7-i of basis index d)
__global__ void vqc_setup(const float* __restrict__ crz1,
                          const float* __restrict__ crz2,
                          const float* __restrict__ ry1,
                          const float* __restrict__ ry2) {
    int d = threadIdx.x;  // 0..255
    float e1 = 0.f, e2 = 0.f;
#pragma unroll
    for (int i = 0; i < 8; i++) {
        float bc  = (float)((d >> (7 - i)) & 1);
        int   t1  = (i + 1) & 7;
        int   t2  = (i + 7) & 7;
        float bt1 = (float)((d >> (7 - t1)) & 1);
        float bt2 = (float)((d >> (7 - t2)) & 1);
        e1 += bc * (bt1 - 0.5f) * crz1[i];
        e2 += bc * (bt2 - 0.5f) * crz2[i];
    }
    float s, c;
    sincosf(e1, &s, &c); g_diag1[d] = make_float2(c, s);
    sincosf(e2, &s, &c); g_diag2[d] = make_float2(c, s);
    if (d < 8) {
        sincosf(0.5f * ry1[d], &s, &c); g_cs1[d] = make_float2(c, s);
        sincosf(0.5f * ry2[d], &s, &c); g_cs2[d] = make_float2(c, s);
    }
}

// One full RY layer (8 wires) on a warp-resident 256-amplitude state.
// d = lane*8 + r.  Wire i acts on bit (7-i):
//   i = 0..4  -> lane bit (4-i)  (cross-lane, shfl_xor)
//   i = 5..7  -> r bit (7-i)     (in-register)
// Pair rule (bit=0 elem a, bit=1 elem b): a' = c*a - s*b ; b' = s*a + c*b.
__device__ __forceinline__ void apply_layer(float2 a[8], const float2* cs, int lane) {
    // cross-lane wires
#pragma unroll
    for (int i = 0; i < 5; i++) {
        float2 p = cs[i];
        float c = p.x, s = p.y;
        int mask = 1 << (4 - i);
        float ss = (lane & mask) ? s : -s;   // bit0: c*mine - s*other ; bit1: c*mine + s*other
#pragma unroll
        for (int r = 0; r < 8; r++) {
            float ox = __shfl_xor_sync(FULL, a[r].x, mask);
            float oy = __shfl_xor_sync(FULL, a[r].y, mask);
            a[r].x = c * a[r].x + ss * ox;
            a[r].y = c * a[r].y + ss * oy;
        }
    }
    // in-register wires
#pragma unroll
    for (int i = 5; i < 8; i++) {
        float c = cs[i].x, s = cs[i].y;
        int pb = 1 << (7 - i);
#pragma unroll
        for (int r = 0; r < 8; r++) {
            if (r & pb) continue;
            int r2 = r | pb;
            float ax = a[r].x,  ay = a[r].y;
            float bx = a[r2].x, by = a[r2].y;
            a[r].x  = c * ax - s * bx;  a[r].y  = c * ay - s * by;
            a[r2].x = s * ax + c * bx;  a[r2].y = s * ay + c * by;
        }
    }
}

__global__ __launch_bounds__(256)
void vqc_main(const float* __restrict__ x, float* __restrict__ out, int nstates) {
    int warp = (int)((blockIdx.x * blockDim.x + threadIdx.x) >> 5);
    int lane = threadIdx.x & 31;
    if (warp >= nstates) return;

    // ---- encoder angles: lanes 0..7 compute sincos, broadcast to all ----
    float c0 = 1.f, s0 = 0.f;
    if (lane < 8) sincosf(0.5f * x[warp * 8 + lane], &s0, &c0);
    float ec[8], es[8];
#pragma unroll
    for (int p = 0; p < 8; p++) {
        ec[p] = __shfl_sync(FULL, c0, p);
        es[p] = __shfl_sync(FULL, s0, p);
    }

    // ---- initial product state (real), fused with diag1 multiply ----
    // amplitude(d) = prod over bits q of (bit_q(d) ? sin(x_{7-q}/2) : cos(x_{7-q}/2))
    float plane = 1.f;
#pragma unroll
    for (int q = 3; q < 8; q++) {
        int b = (lane >> (q - 3)) & 1;
        plane *= b ? es[7 - q] : ec[7 - q];
    }
    float2 a[8];
#pragma unroll
    for (int r = 0; r < 8; r++) {
        float f = plane;
        f *= (r & 1) ? es[7] : ec[7];
        f *= (r & 2) ? es[6] : ec[6];
        f *= (r & 4) ? es[5] : ec[5];
        float2 d1 = g_diag1[lane * 8 + r];   // state real -> complex scale
        a[r].x = f * d1.x;
        a[r].y = f * d1.y;
    }

    // ---- RY1 layer ----
    apply_layer(a, g_cs1, lane);

    // ---- diag2 (complex * complex) ----
#pragma unroll
    for (int r = 0; r < 8; r++) {
        float2 d2 = g_diag2[lane * 8 + r];
        float xr = a[r].x, yi = a[r].y;
        a[r].x = xr * d2.x - yi * d2.y;
        a[r].y = xr * d2.y + yi * d2.x;
    }

    // ---- RY2 layer ----
    apply_layer(a, g_cs2, lane);

    // ---- measurement: out[w] = sum_d (1 - 2*bit_{7-w}(d)) * |psi_d|^2 ----
    float T = 0.f, s5 = 0.f, s6 = 0.f, s7 = 0.f;
#pragma unroll
    for (int r = 0; r < 8; r++) {
        float p = a[r].x * a[r].x + a[r].y * a[r].y;
        T  += p;
        s5 += (r & 4) ? -p : p;   // wire 5 <-> r bit 2
        s6 += (r & 2) ? -p : p;   // wire 6 <-> r bit 1
        s7 += (r & 1) ? -p : p;   // wire 7 <-> r bit 0
    }
    // plain warp sums for wires 5,6,7
#pragma unroll
    for (int m = 1; m < 32; m <<= 1) {
        s5 += __shfl_xor_sync(FULL, s5, m);
        s6 += __shfl_xor_sync(FULL, s6, m);
        s7 += __shfl_xor_sync(FULL, s7, m);
    }
    // signed Walsh-Hadamard butterfly on per-lane total prob T:
    // after 5 stages lane l holds sum_m (-1)^{popc(l & m)} T_m.
    // Lane (1<<q) therefore holds wire (4-q)'s expectation.
    float h = T;
#pragma unroll
    for (int q = 0; q < 5; q++) {
        float o = __shfl_xor_sync(FULL, h, 1 << q);
        h = (lane & (1 << q)) ? (o - h) : (h + o);
    }
    float o0 = __shfl_sync(FULL, h, 16);  // wire 0
    float o1 = __shfl_sync(FULL, h, 8);   // wire 1
    float o2 = __shfl_sync(FULL, h, 4);   // wire 2
    float o3 = __shfl_sync(FULL, h, 2);   // wire 3
    float o4 = __shfl_sync(FULL, h, 1);   // wire 4

    if (lane < 8) {
        float v;
        switch (lane) {
            case 0: v = o0; break;
            case 1: v = o1; break;
            case 2: v = o2; break;
            case 3: v = o3; break;
            case 4: v = o4; break;
            case 5: v = s5; break;
            case 6: v = s6; break;
            default: v = s7; break;
        }
        out[warp * 8 + lane] = v;
    }
}

extern "C" void kernel_launch(void* const* d_in, const int* in_sizes, int n_in,
                              void* d_out, int out_size) {
    const float* x    = (const float*)d_in[0];  // input_features (4,4096,8)
    const float* ry1  = (const float*)d_in[1];  // params_ry1 (1,8)
    const float* crz1 = (const float*)d_in[2];  // params_crz1 (1,8)
    const float* ry2  = (const float*)d_in[3];  // params_ry2 (1,8)
    const float* crz2 = (const float*)d_in[4];  // params_crz2 (1,8)
    float* out = (float*)d_out;

    int nstates = in_sizes[0] / 8;              // 16384

    vqc_setup<<<1, 256>>>(crz1, crz2, ry1, ry2);

    const int warps_per_block = 8;              // 256 threads
    int blocks = (nstates + warps_per_block - 1) / warps_per_block;
    vqc_main<<<blocks, warps_per_block * 32>>>(x, out, nstates);
}

// round 2
// speedup vs baseline: 1.1221x; 1.1221x over previous
#include <cuda_runtime.h>
#include <cuda_bf16.h>

#define FULL 0xffffffffu
typedef unsigned long long u64;

// ---------- packed f32x2 helpers (SASS FFMA2 path, PTX-only) ----------
__device__ __forceinline__ u64 pack2(float x, float y) {
    u64 r; asm("mov.b64 %0, {%1, %2};" : "=l"(r) : "f"(x), "f"(y)); return r;
}
__device__ __forceinline__ float2 unpack2(u64 v) {
    float2 f; asm("mov.b64 {%0, %1}, %2;" : "=f"(f.x), "=f"(f.y) : "l"(v)); return f;
}
__device__ __forceinline__ u64 mul2(u64 a, u64 b) {
    u64 d; asm("mul.rn.f32x2 %0, %1, %2;" : "=l"(d) : "l"(a), "l"(b)); return d;
}
__device__ __forceinline__ u64 fma2(u64 a, u64 b, u64 c) {
    u64 d; asm("fma.rn.f32x2 %0, %1, %2, %3;" : "=l"(d) : "l"(a), "l"(b), "l"(c)); return d;
}

// Precomputed per-launch constants (params only). No allocation allowed ->
// __device__ globals.
__device__ u64    g_diag1[256];   // packed (cos, sin) of CRZ block 1 phase
__device__ u64    g_diag2[256];   // packed (cos, sin) of CRZ block 2 phase
__device__ float2 g_cs1[8];       // (cos, sin) of ry1[i]/2
__device__ float2 g_cs2[8];       // (cos, sin) of ry2[i]/2

// bits[d, i] = (d >> (7-i)) & 1  (wire i <-> bit 7-i of basis index d)
__global__ void vqc_setup(const float* __restrict__ crz1,
                          const float* __restrict__ crz2,
                          const float* __restrict__ ry1,
                          const float* __restrict__ ry2) {
    int d = threadIdx.x;  // 0..255
    float e1 = 0.f, e2 = 0.f;
#pragma unroll
    for (int i = 0; i < 8; i++) {
        float bc  = (float)((d >> (7 - i)) & 1);
        int   t1  = (i + 1) & 7;
        int   t2  = (i + 7) & 7;
        float bt1 = (float)((d >> (7 - t1)) & 1);
        float bt2 = (float)((d >> (7 - t2)) & 1);
        e1 += bc * (bt1 - 0.5f) * crz1[i];
        e2 += bc * (bt2 - 0.5f) * crz2[i];
    }
    float s, c;
    sincosf(e1, &s, &c); g_diag1[d] = pack2(c, s);
    sincosf(e2, &s, &c); g_diag2[d] = pack2(c, s);
    if (d < 8) {
        sincosf(0.5f * ry1[d], &s, &c); g_cs1[d] = make_float2(c, s);
        sincosf(0.5f * ry2[d], &s, &c); g_cs2[d] = make_float2(c, s);
    }
}

// Layout: 8 lanes per state, 4 states per warp. d = r*8 + sub, r=0..31 in
// registers, sub = lane & 7.  Wire i acts on d-bit (7-i):
//   wires 0..4 -> r bits 4..0   (in-register butterflies)
//   wires 5..7 -> sub bits 2..0 (cross-lane, shfl_xor masks 4,2,1 inside group)
// Pair rule (bit=0 elem a, bit=1 elem b): a' = c*a - s*b ; b' = s*a + c*b.
__device__ __forceinline__ void apply_layer(u64 a[32], const float2* cs, int sub) {
    // in-register wires 0..4 (r bit 4-q)
#pragma unroll
    for (int q = 0; q < 5; q++) {
        float2 p = cs[q];
        u64 c2  = pack2(p.x,  p.x);
        u64 s2  = pack2(p.y,  p.y);
        u64 ns2 = pack2(-p.y, -p.y);
        int pb = 1 << (4 - q);
#pragma unroll
        for (int r = 0; r < 32; r++) {
            if (r & pb) continue;
            int r2 = r | pb;
            u64 t  = mul2(ns2, a[r2]);
            u64 u  = mul2(s2,  a[r]);
            u64 nr = fma2(c2, a[r],  t);
            a[r2]  = fma2(c2, a[r2], u);
            a[r]   = nr;
        }
    }
    // cross-lane wires 5,6,7 (sub bit 7-q -> shfl mask 4,2,1)
#pragma unroll
    for (int q = 5; q < 8; q++) {
        float2 p = cs[q];
        int mask = 1 << (7 - q);
        u64 c2 = pack2(p.x, p.x);
        float ss = (sub & mask) ? p.y : -p.y;  // bit0: c*mine - s*other ; bit1: c*mine + s*other
        u64 ss2 = pack2(ss, ss);
#pragma unroll
        for (int r = 0; r < 32; r++) {
            float2 f = unpack2(a[r]);
            float ox = __shfl_xor_sync(FULL, f.x, mask);
            float oy = __shfl_xor_sync(FULL, f.y, mask);
            a[r] = fma2(c2, a[r], mul2(ss2, pack2(ox, oy)));
        }
    }
}

__global__ __launch_bounds__(256)
void vqc_main(const float* __restrict__ x, float* __restrict__ out, int nstates) {
    int tid  = blockIdx.x * blockDim.x + threadIdx.x;
    int warp = tid >> 5;
    int lane = threadIdx.x & 31;
    int sub  = lane & 7;
    int gbase = lane & 24;           // first lane of my 8-lane group
    if (warp * 4 >= nstates) return;

    // ---- encoder: one fully coalesced load, sincos, broadcast in group ----
    float xv = x[warp * 32 + lane];  // lane -> (state=g, wire=sub)
    float s0, c0;
    sincosf(0.5f * xv, &s0, &c0);
    float ec[8], es[8];
#pragma unroll
    for (int i = 0; i < 8; i++) {
        ec[i] = __shfl_sync(FULL, c0, gbase | i);
        es[i] = __shfl_sync(FULL, s0, gbase | i);
    }

    // ---- initial product state, fused with diag1 ----
    // amplitude(d) = prod_i (bit(7-i,d) ? sin(x_i/2) : cos(x_i/2))
    float f01[4], f234[8];
#pragma unroll
    for (int j = 0; j < 4; j++)
        f01[j] = ((j & 2) ? es[0] : ec[0]) * ((j & 1) ? es[1] : ec[1]);
#pragma unroll
    for (int j = 0; j < 8; j++)
        f234[j] = ((j & 4) ? es[2] : ec[2]) *
                  (((j & 2) ? es[3] : ec[3]) * ((j & 1) ? es[4] : ec[4]));
    float plane = ((sub & 4) ? es[5] : ec[5]) *
                  (((sub & 2) ? es[6] : ec[6]) * ((sub & 1) ? es[7] : ec[7]));
    u64 a[32];
#pragma unroll
    for (int r = 0; r < 32; r++) {
        float amp = plane * (f01[r >> 3] * f234[r & 7]);
        a[r] = mul2(pack2(amp, amp), g_diag1[r * 8 + sub]);
    }

    // ---- RY1 layer ----
    apply_layer(a, g_cs1, sub);

    // ---- diag2 (complex * complex) ----
#pragma unroll
    for (int r = 0; r < 32; r++) {
        float2 f = unpack2(a[r]);
        float2 d = unpack2(g_diag2[r * 8 + sub]);
        a[r] = pack2(f.x * d.x - f.y * d.y, f.x * d.y + f.y * d.x);
    }

    // ---- RY2 layer ----
    apply_layer(a, g_cs2, sub);

    // ---- measurement: out[w] = sum_d (1 - 2*bit(7-w,d)) * |psi_d|^2 ----
    float p[32];
#pragma unroll
    for (int r = 0; r < 32; r++) {
        float2 f = unpack2(a[r]);
        p[r] = f.x * f.x + f.y * f.y;
    }
    // tree over r bits: bit0<->wire4, bit1<->wire3, ... bit4<->wire0
    float o0, o1 = 0.f, o2 = 0.f, o3 = 0.f, o4 = 0.f, T;
    float l1[16];
#pragma unroll
    for (int i = 0; i < 16; i++) { l1[i] = p[2*i] + p[2*i+1];  o4 += p[2*i] - p[2*i+1]; }
    float l2[8];
#pragma unroll
    for (int i = 0; i < 8; i++)  { l2[i] = l1[2*i] + l1[2*i+1]; o3 += l1[2*i] - l1[2*i+1]; }
    float l3[4];
#pragma unroll
    for (int i = 0; i < 4; i++)  { l3[i] = l2[2*i] + l2[2*i+1]; o2 += l2[2*i] - l2[2*i+1]; }
    float l4[2];
#pragma unroll
    for (int i = 0; i < 2; i++)  { l4[i] = l3[2*i] + l3[2*i+1]; o1 += l3[2*i] - l3[2*i+1]; }
    o0 = l4[0] - l4[1];
    T  = l4[0] + l4[1];

    // sum o0..o4 across the 8 lanes of the group
#pragma unroll
    for (int m = 1; m < 8; m <<= 1) {
        o0 += __shfl_xor_sync(FULL, o0, m);
        o1 += __shfl_xor_sync(FULL, o1, m);
        o2 += __shfl_xor_sync(FULL, o2, m);
        o3 += __shfl_xor_sync(FULL, o3, m);
        o4 += __shfl_xor_sync(FULL, o4, m);
    }
    // signed Walsh butterfly on T over the 3 sub bits:
    // lane with sub=1<<q holds wire (7-q)'s expectation
    float h = T;
#pragma unroll
    for (int q = 0; q < 3; q++) {
        float o = __shfl_xor_sync(FULL, h, 1 << q);
        h = (lane & (1 << q)) ? (o - h) : (h + o);
    }
    float v5 = __shfl_sync(FULL, h, gbase | 4);
    float v6 = __shfl_sync(FULL, h, gbase | 2);
    float v7 = __shfl_sync(FULL, h, gbase | 1);

    float v;
    switch (sub) {
        case 0: v = o0; break;
        case 1: v = o1; break;
        case 2: v = o2; break;
        case 3: v = o3; break;
        case 4: v = o4; break;
        case 5: v = v5; break;
        case 6: v = v6; break;
        default: v = v7; break;
    }
    out[warp * 32 + lane] = v;   // fully coalesced
}

extern "C" void kernel_launch(void* const* d_in, const int* in_sizes, int n_in,
                              void* d_out, int out_size) {
    const float* x    = (const float*)d_in[0];  // input_features (4,4096,8)
    const float* ry1  = (const float*)d_in[1];  // params_ry1 (1,8)
    const float* crz1 = (const float*)d_in[2];  // params_crz1 (1,8)
    const float* ry2  = (const float*)d_in[3];  // params_ry2 (1,8)
    const float* crz2 = (const float*)d_in[4];  // params_crz2 (1,8)
    float* out = (float*)d_out;

    int nstates = in_sizes[0] / 8;              // 16384

    vqc_setup<<<1, 256>>>(crz1, crz2, ry1, ry2);

    // 4 states per warp, 8 warps per block -> 32 states per block
    int blocks = (nstates + 31) / 32;
    vqc_main<<<blocks, 256>>>(x, out, nstates);
}

// round 3
// speedup vs baseline: 1.4848x; 1.3232x over previous
#include <cuda_runtime.h>
#include <cuda_bf16.h>

#define FULL 0xffffffffu
typedef unsigned long long u64;

// ---------- packed f32x2 helpers (SASS FFMA2 path, PTX-only) ----------
__device__ __forceinline__ u64 pack2(float x, float y) {
    u64 r; asm("mov.b64 %0, {%1, %2};" : "=l"(r) : "f"(x), "f"(y)); return r;
}
__device__ __forceinline__ float2 unpack2(u64 v) {
    float2 f; asm("mov.b64 {%0, %1}, %2;" : "=f"(f.x), "=f"(f.y) : "l"(v)); return f;
}
__device__ __forceinline__ u64 mul2(u64 a, u64 b) {
    u64 d; asm("mul.rn.f32x2 %0, %1, %2;" : "=l"(d) : "l"(a), "l"(b)); return d;
}
__device__ __forceinline__ u64 fma2(u64 a, u64 b, u64 c) {
    u64 d; asm("fma.rn.f32x2 %0, %1, %2, %3;" : "=l"(d) : "l"(a), "l"(b), "l"(c)); return d;
}

// Precomputed per-launch constants (params only). No allocation allowed ->
// __device__ globals.
__device__ u64    g_diag1[256];   // packed (cos, sin) of CRZ block 1 phase
__device__ u64    g_diag2[256];   // packed (cos, sin) of CRZ block 2 phase
__device__ float2 g_cs1[8];       // (cos, sin) of ry1[i]/2
__device__ float2 g_cs2[8];       // (cos, sin) of ry2[i]/2

// bits[d, i] = (d >> (7-i)) & 1  (wire i <-> bit 7-i of basis index d)
__global__ void vqc_setup(const float* __restrict__ crz1,
                          const float* __restrict__ crz2,
                          const float* __restrict__ ry1,
                          const float* __restrict__ ry2) {
    int d = threadIdx.x;  // 0..255
    float e1 = 0.f, e2 = 0.f;
#pragma unroll
    for (int i = 0; i < 8; i++) {
        float bc  = (float)((d >> (7 - i)) & 1);
        int   t1  = (i + 1) & 7;
        int   t2  = (i + 7) & 7;
        float bt1 = (float)((d >> (7 - t1)) & 1);
        float bt2 = (float)((d >> (7 - t2)) & 1);
        e1 += bc * (bt1 - 0.5f) * crz1[i];
        e2 += bc * (bt2 - 0.5f) * crz2[i];
    }
    float s, c;
    sincosf(e1, &s, &c); g_diag1[d] = pack2(c, s);
    sincosf(e2, &s, &c); g_diag2[d] = pack2(c, s);
    if (d < 8) {
        sincosf(0.5f * ry1[d], &s, &c); g_cs1[d] = make_float2(c, s);
        sincosf(0.5f * ry2[d], &s, &c); g_cs2[d] = make_float2(c, s);
    }
}

// Layout: 8 lanes per state, 4 states per warp. d = r*8 + sub, r=0..31 in
// registers, sub = lane & 7.  Wire i acts on d-bit (7-i):
//   wires 0..4 -> r bits 4..0   (in-register butterflies)
//   wires 5..7 -> sub bits 2..0 (cross-lane, shfl_xor masks 4,2,1 inside group)
// Pair rule (bit=0 elem a, bit=1 elem b): a' = c*a - s*b ; b' = s*a + c*b.
__device__ __forceinline__ void apply_layer(u64 a[32], const float2* cs, int sub) {
    // in-register wires 0..4 (r bit 4-q)
#pragma unroll
    for (int q = 0; q < 5; q++) {
        float2 p = cs[q];
        u64 c2  = pack2(p.x,  p.x);
        u64 s2  = pack2(p.y,  p.y);
        u64 ns2 = pack2(-p.y, -p.y);
        int pb = 1 << (4 - q);
#pragma unroll
        for (int r = 0; r < 32; r++) {
            if (r & pb) continue;
            int r2 = r | pb;
            u64 t  = mul2(ns2, a[r2]);
            u64 u  = mul2(s2,  a[r]);
            u64 nr = fma2(c2, a[r],  t);
            a[r2]  = fma2(c2, a[r2], u);
            a[r]   = nr;
        }
    }
    // cross-lane wires 5,6,7 (sub bit 7-q -> shfl mask 4,2,1)
#pragma unroll
    for (int q = 5; q < 8; q++) {
        float2 p = cs[q];
        int mask = 1 << (7 - q);
        u64 c2 = pack2(p.x, p.x);
        float ss = (sub & mask) ? p.y : -p.y;  // bit0: c*mine - s*other ; bit1: c*mine + s*other
        u64 ss2 = pack2(ss, ss);
#pragma unroll
        for (int r = 0; r < 32; r++) {
            float2 f = unpack2(a[r]);
            float ox = __shfl_xor_sync(FULL, f.x, mask);
            float oy = __shfl_xor_sync(FULL, f.y, mask);
            a[r] = fma2(c2, a[r], mul2(ss2, pack2(ox, oy)));
        }
    }
}

__global__ __launch_bounds__(128, 6)
void vqc_main(const float* __restrict__ x, float* __restrict__ out, int nstates) {
    int tid  = blockIdx.x * blockDim.x + threadIdx.x;
    int warp = tid >> 5;
    int lane = threadIdx.x & 31;
    int sub  = lane & 7;
    int gbase = lane & 24;           // first lane of my 8-lane group
    if (warp * 4 >= nstates) return;

    // ---- encoder: one fully coalesced load, sincos, broadcast in group ----
    float xv = x[warp * 32 + lane];  // lane -> (state=g, wire=sub)
    float s0, c0;
    sincosf(0.5f * xv, &s0, &c0);
    float ec[8], es[8];
#pragma unroll
    for (int i = 0; i < 8; i++) {
        ec[i] = __shfl_sync(FULL, c0, gbase | i);
        es[i] = __shfl_sync(FULL, s0, gbase | i);
    }

    // ---- initial product state, fused with diag1 ----
    // amplitude(d) = prod_i (bit(7-i,d) ? sin(x_i/2) : cos(x_i/2))
    float f01[4], f234[8];
#pragma unroll
    for (int j = 0; j < 4; j++)
        f01[j] = ((j & 2) ? es[0] : ec[0]) * ((j & 1) ? es[1] : ec[1]);
#pragma unroll
    for (int j = 0; j < 8; j++)
        f234[j] = ((j & 4) ? es[2] : ec[2]) *
                  (((j & 2) ? es[3] : ec[3]) * ((j & 1) ? es[4] : ec[4]));
    float plane = ((sub & 4) ? es[5] : ec[5]) *
                  (((sub & 2) ? es[6] : ec[6]) * ((sub & 1) ? es[7] : ec[7]));
    u64 a[32];
#pragma unroll
    for (int r = 0; r < 32; r++) {
        float amp = plane * (f01[r >> 3] * f234[r & 7]);
        a[r] = mul2(pack2(amp, amp), g_diag1[r * 8 + sub]);
    }

    // ---- RY1 layer ----
    apply_layer(a, g_cs1, sub);

    // ---- diag2 (complex * complex) ----
#pragma unroll
    for (int r = 0; r < 32; r++) {
        float2 f = unpack2(a[r]);
        float2 d = unpack2(g_diag2[r * 8 + sub]);
        a[r] = pack2(f.x * d.x - f.y * d.y, f.x * d.y + f.y * d.x);
    }

    // ---- RY2 layer ----
    apply_layer(a, g_cs2, sub);

    // ---- measurement: out[w] = sum_d (1 - 2*bit(7-w,d)) * |psi_d|^2 ----
    float p[32];
#pragma unroll
    for (int r = 0; r < 32; r++) {
        float2 f = unpack2(a[r]);
        p[r] = f.x * f.x + f.y * f.y;
    }
    // tree over r bits: bit0<->wire4, bit1<->wire3, ... bit4<->wire0
    float o0, o1 = 0.f, o2 = 0.f, o3 = 0.f, o4 = 0.f, T;
    float l1[16];
#pragma unroll
    for (int i = 0; i < 16; i++) { l1[i] = p[2*i] + p[2*i+1];  o4 += p[2*i] - p[2*i+1]; }
    float l2[8];
#pragma unroll
    for (int i = 0; i < 8; i++)  { l2[i] = l1[2*i] + l1[2*i+1]; o3 += l1[2*i] - l1[2*i+1]; }
    float l3[4];
#pragma unroll
    for (int i = 0; i < 4; i++)  { l3[i] = l2[2*i] + l2[2*i+1]; o2 += l2[2*i] - l2[2*i+1]; }
    float l4[2];
#pragma unroll
    for (int i = 0; i < 2; i++)  { l4[i] = l3[2*i] + l3[2*i+1]; o1 += l3[2*i] - l3[2*i+1]; }
    o0 = l4[0] - l4[1];
    T  = l4[0] + l4[1];

    // sum o0..o4 across the 8 lanes of the group
#pragma unroll
    for (int m = 1; m < 8; m <<= 1) {
        o0 += __shfl_xor_sync(FULL, o0, m);
        o1 += __shfl_xor_sync(FULL, o1, m);
        o2 += __shfl_xor_sync(FULL, o2, m);
        o3 += __shfl_xor_sync(FULL, o3, m);
        o4 += __shfl_xor_sync(FULL, o4, m);
    }
    // signed Walsh butterfly on T over the 3 sub bits:
    // lane with sub=1<<q holds wire (7-q)'s expectation
    float h = T;
#pragma unroll
    for (int q = 0; q < 3; q++) {
        float o = __shfl_xor_sync(FULL, h, 1 << q);
        h = (lane & (1 << q)) ? (o - h) : (h + o);
    }
    float v5 = __shfl_sync(FULL, h, gbase | 4);
    float v6 = __shfl_sync(FULL, h, gbase | 2);
    float v7 = __shfl_sync(FULL, h, gbase | 1);

    float v;
    switch (sub) {
        case 0: v = o0; break;
        case 1: v = o1; break;
        case 2: v = o2; break;
        case 3: v = o3; break;
        case 4: v = o4; break;
        case 5: v = v5; break;
        case 6: v = v6; break;
        default: v = v7; break;
    }
    out[warp * 32 + lane] = v;   // fully coalesced
}

extern "C" void kernel_launch(void* const* d_in, const int* in_sizes, int n_in,
                              void* d_out, int out_size) {
    const float* x    = (const float*)d_in[0];  // input_features (4,4096,8)
    const float* ry1  = (const float*)d_in[1];  // params_ry1 (1,8)
    const float* crz1 = (const float*)d_in[2];  // params_crz1 (1,8)
    const float* ry2  = (const float*)d_in[3];  // params_ry2 (1,8)
    const float* crz2 = (const float*)d_in[4];  // params_crz2 (1,8)
    float* out = (float*)d_out;

    int nstates = in_sizes[0] / 8;              // 16384

    vqc_setup<<<1, 256>>>(crz1, crz2, ry1, ry2);

    // 4 states per warp, 4 warps per block -> 16 states per block
    int blocks = (nstates + 15) / 16;
    vqc_main<<<blocks, 128>>>(x, out, nstates);
}

// round 4
// speedup vs baseline: 1.7738x; 1.1946x over previous
#include <cuda_runtime.h>
#include <cuda_bf16.h>

#define FULL 0xffffffffu
typedef unsigned long long u64;

// ---------- packed f32x2 helpers (SASS FFMA2 path, PTX-only) ----------
__device__ __forceinline__ u64 pack2(float x, float y) {
    u64 r; asm("mov.b64 %0, {%1, %2};" : "=l"(r) : "f"(x), "f"(y)); return r;
}
__device__ __forceinline__ float2 unpack2(u64 v) {
    float2 f; asm("mov.b64 {%0, %1}, %2;" : "=f"(f.x), "=f"(f.y) : "l"(v)); return f;
}
__device__ __forceinline__ u64 mul2(u64 a, u64 b) {
    u64 d; asm("mul.rn.f32x2 %0, %1, %2;" : "=l"(d) : "l"(a), "l"(b)); return d;
}
__device__ __forceinline__ u64 fma2(u64 a, u64 b, u64 c) {
    u64 d; asm("fma.rn.f32x2 %0, %1, %2, %3;" : "=l"(d) : "l"(a), "l"(b), "l"(c)); return d;
}

// Precomputed per-launch constants (params only). __device__ globals (no alloc).
__device__ u64    g_diag1[256];    // packed (cos, sin) of CRZ block 1 phase
__device__ u64    g_diag2a[256];   // packed ( c,  s) of CRZ block 2 phase
__device__ u64    g_diag2b[256];   // packed (-s,  c)
__device__ float2 g_cs1[8];        // (cos, sin) of ry1[i]/2
__device__ float2 g_cs2[8];        // (cos, sin) of ry2[i]/2

// bits[d, i] = (d >> (7-i)) & 1  (wire i <-> bit 7-i of basis index d)
__global__ void vqc_setup(const float* __restrict__ crz1,
                          const float* __restrict__ crz2,
                          const float* __restrict__ ry1,
                          const float* __restrict__ ry2) {
    int d = threadIdx.x;  // 0..255
    float e1 = 0.f, e2 = 0.f;
#pragma unroll
    for (int i = 0; i < 8; i++) {
        float bc  = (float)((d >> (7 - i)) & 1);
        int   t1  = (i + 1) & 7;
        int   t2  = (i + 7) & 7;
        float bt1 = (float)((d >> (7 - t1)) & 1);
        float bt2 = (float)((d >> (7 - t2)) & 1);
        e1 += bc * (bt1 - 0.5f) * crz1[i];
        e2 += bc * (bt2 - 0.5f) * crz2[i];
    }
    float s, c;
    sincosf(e1, &s, &c); g_diag1[d]  = pack2(c, s);
    sincosf(e2, &s, &c); g_diag2a[d] = pack2(c, s);
    g_diag2b[d] = pack2(-s, c);
    if (d < 8) {
        sincosf(0.5f * ry1[d], &s, &c); g_cs1[d] = make_float2(c, s);
        sincosf(0.5f * ry2[d], &s, &c); g_cs2[d] = make_float2(c, s);
    }
}

// Layout: 16 lanes per state, 2 states per warp, 16 amps per thread.
// d = r*16 + sub, r = 0..15 in registers, sub = lane & 15.
// Wire i acts on d-bit (7-i):
//   wires 0..3 -> r bits 3..0    (in-register butterflies, pb = 8,4,2,1)
//   wires 4..7 -> sub bits 3..0  (cross-lane shfl_xor masks 8,4,2,1; stays in group)
// Pair rule (bit=0 elem a, bit=1 elem b): a' = c*a - s*b ; b' = s*a + c*b.
__device__ __forceinline__ void apply_layer(u64 a[16], const float2* cs, int sub) {
    // in-register wires 0..3
#pragma unroll
    for (int q = 0; q < 4; q++) {
        float2 p = cs[q];
        u64 c2  = pack2(p.x,  p.x);
        u64 s2  = pack2(p.y,  p.y);
        u64 ns2 = pack2(-p.y, -p.y);
        int pb = 1 << (3 - q);
#pragma unroll
        for (int r = 0; r < 16; r++) {
            if (r & pb) continue;
            int r2 = r | pb;
            u64 t  = mul2(ns2, a[r2]);
            u64 u  = mul2(s2,  a[r]);
            u64 nr = fma2(c2, a[r],  t);
            a[r2]  = fma2(c2, a[r2], u);
            a[r]   = nr;
        }
    }
    // cross-lane wires 4..7 (sub bit 7-q -> shfl mask 8,4,2,1)
#pragma unroll
    for (int q = 4; q < 8; q++) {
        float2 p = cs[q];
        int mask = 1 << (7 - q);
        u64 c2 = pack2(p.x, p.x);
        float ss = (sub & mask) ? p.y : -p.y;  // bit0: c*mine - s*other ; bit1: +s*other
        u64 ss2 = pack2(ss, ss);
#pragma unroll
        for (int r = 0; r < 16; r++) {
            float2 f = unpack2(a[r]);
            float ox = __shfl_xor_sync(FULL, f.x, mask);
            float oy = __shfl_xor_sync(FULL, f.y, mask);
            a[r] = fma2(c2, a[r], mul2(ss2, pack2(ox, oy)));
        }
    }
}

__global__ __launch_bounds__(128, 8)
void vqc_main(const float* __restrict__ x, float* __restrict__ out, int nstates) {
    int tid  = blockIdx.x * blockDim.x + threadIdx.x;
    int warp = tid >> 5;
    int lane = threadIdx.x & 31;
    int sub  = lane & 15;
    int gsel = (lane >> 4) << 3;     // 0 for group 0, 8 for group 1
    if (warp * 2 >= nstates) return;

    // ---- encoder: every lane loads (duplicated across groups, in bounds) ----
    float xv = x[warp * 16 + sub];   // sub -> (state = sub>>3, wire = sub&7)
    float s0, c0;
    __sincosf(0.5f * xv, &s0, &c0);
    // wire i of my group's state lives at source lane gsel + i
    float ec[8], es[8];
#pragma unroll
    for (int i = 0; i < 8; i++) {
        ec[i] = __shfl_sync(FULL, c0, gsel | i);
        es[i] = __shfl_sync(FULL, s0, gsel | i);
    }

    // ---- initial product state, fused with diag1 ----
    // amp(d) = prod_i (bit(7-i,d) ? sin(x_i/2) : cos(x_i/2))
    float plane = ((sub & 8) ? es[4] : ec[4]) *
                  (((sub & 4) ? es[5] : ec[5]) *
                   (((sub & 2) ? es[6] : ec[6]) * ((sub & 1) ? es[7] : ec[7])));
    float f01[4], f23[4];
#pragma unroll
    for (int j = 0; j < 4; j++) {
        f01[j] = (((j & 2) ? es[0] : ec[0]) * ((j & 1) ? es[1] : ec[1])) * plane;
        f23[j] = ((j & 2) ? es[2] : ec[2]) * ((j & 1) ? es[3] : ec[3]);
    }
    u64 a[16];
#pragma unroll
    for (int r = 0; r < 16; r++) {
        float amp = f01[r >> 2] * f23[r & 3];
        a[r] = mul2(pack2(amp, amp), g_diag1[r * 16 + sub]);
    }

    // ---- RY1 layer ----
    apply_layer(a, g_cs1, sub);

    // ---- diag2: complex multiply, packed: res = (x,x)*(c,s) + (y,y)*(-s,c) ----
#pragma unroll
    for (int r = 0; r < 16; r++) {
        float2 f = unpack2(a[r]);
        int d = r * 16 + sub;
        a[r] = fma2(pack2(f.x, f.x), g_diag2a[d],
                    mul2(pack2(f.y, f.y), g_diag2b[d]));
    }

    // ---- RY2 layer ----
    apply_layer(a, g_cs2, sub);

    // ---- measurement: out[w] = sum_d (1 - 2*bit(7-w,d)) * |psi_d|^2 ----
    float p[16];
#pragma unroll
    for (int r = 0; r < 16; r++) {
        float2 f = unpack2(a[r]);
        p[r] = f.x * f.x + f.y * f.y;
    }
    // tree over r bits: bit0<->wire3, bit1<->wire2, bit2<->wire1, bit3<->wire0
    float o0, o1 = 0.f, o2 = 0.f, o3 = 0.f, T;
    float l1[8];
#pragma unroll
    for (int i = 0; i < 8; i++) { l1[i] = p[2*i] + p[2*i+1];  o3 += p[2*i] - p[2*i+1]; }
    float l2[4];
#pragma unroll
    for (int i = 0; i < 4; i++) { l2[i] = l1[2*i] + l1[2*i+1]; o2 += l1[2*i] - l1[2*i+1]; }
    float l3[2];
#pragma unroll
    for (int i = 0; i < 2; i++) { l3[i] = l2[2*i] + l2[2*i+1]; o1 += l2[2*i] - l2[2*i+1]; }
    o0 = l3[0] - l3[1];
    T  = l3[0] + l3[1];

    // sum o0..o3 across the 16 lanes of the group (masks stay in group)
#pragma unroll
    for (int m = 1; m < 16; m <<= 1) {
        o0 += __shfl_xor_sync(FULL, o0, m);
        o1 += __shfl_xor_sync(FULL, o1, m);
        o2 += __shfl_xor_sync(FULL, o2, m);
        o3 += __shfl_xor_sync(FULL, o3, m);
    }
    // signed Walsh butterfly on T over the 4 sub bits:
    // lane with sub = 1<<q holds wire (7-q)'s expectation
    float h = T;
#pragma unroll
    for (int q = 0; q < 4; q++) {
        float o = __shfl_xor_sync(FULL, h, 1 << q);
        h = (lane & (1 << q)) ? (o - h) : (h + o);
    }
    int gb = lane & 16;
    float v4 = __shfl_sync(FULL, h, gb | 8);
    float v5 = __shfl_sync(FULL, h, gb | 4);
    float v6 = __shfl_sync(FULL, h, gb | 2);
    float v7 = __shfl_sync(FULL, h, gb | 1);

    if (sub < 8) {
        float v;
        switch (sub) {
            case 0: v = o0; break;
            case 1: v = o1; break;
            case 2: v = o2; break;
            case 3: v = o3; break;
            case 4: v = v4; break;
            case 5: v = v5; break;
            case 6: v = v6; break;
            default: v = v7; break;
        }
        // (state = lane>>4, wire = sub) -> contiguous 16 floats per warp
        out[warp * 16 + gsel + sub] = v;
    }
}

extern "C" void kernel_launch(void* const* d_in, const int* in_sizes, int n_in,
                              void* d_out, int out_size) {
    const float* x    = (const float*)d_in[0];  // input_features (4,4096,8)
    const float* ry1  = (const float*)d_in[1];  // params_ry1 (1,8)
    const float* crz1 = (const float*)d_in[2];  // params_crz1 (1,8)
    const float* ry2  = (const float*)d_in[3];  // params_ry2 (1,8)
    const float* crz2 = (const float*)d_in[4];  // params_crz2 (1,8)
    float* out = (float*)d_out;

    int nstates = in_sizes[0] / 8;              // 16384

    vqc_setup<<<1, 256>>>(crz1, crz2, ry1, ry2);

    // 2 states per warp, 4 warps per block -> 8 states per block
    int blocks = (nstates + 7) / 8;
    vqc_main<<<blocks, 128>>>(x, out, nstates);
}